// round 1
// baseline (speedup 1.0000x reference)
#include <cuda_runtime.h>

#define HH 512
#define WW 512
#define DH 256
#define HWp (HH*WW)          // 262144
#define BB 2
#define MROWS (BB*HWp)       // 524288

// ---------------- scratch (device globals; no allocation allowed) ----------
__device__ float g_down_x[BB*3*DH*DH];                 // 1.5 MB
__device__ float g_actA[(size_t)MROWS*128];            // 256 MB
__device__ float g_actB[(size_t)MROWS*128];            // 256 MB (also holds local_weight 524288x81)
__device__ float g_out_full[BB*3*HH*WW];               // 6 MB
__device__ float g_out256[BB*3*DH*DH];                 // 1.5 MB
__device__ float g_feat_tmp[BB*64*128*128];            // 8 MB

// ---------------- bicubic tap helpers (match jax.image.resize, a=-0.5) -----
__device__ __forceinline__ void taps_down2(int o, int n, int idx[4], float w[4]) {
    const float kw0 = -0.0625f, kw1 = 0.5625f;
    float kw[4] = {kw0, kw1, kw1, kw0};
    float s = 0.f;
#pragma unroll
    for (int t = 0; t < 4; ++t) {
        int i = 2*o - 1 + t;
        bool ok = (i >= 0) && (i < n);
        idx[t] = ok ? i : 0;
        w[t]   = ok ? kw[t] : 0.f;
        s += w[t];
    }
    float inv = 1.f / s;
#pragma unroll
    for (int t = 0; t < 4; ++t) w[t] *= inv;
}

__device__ __forceinline__ void taps_up2(int o, int n, int idx[4], float w[4]) {
    // output size 2n; sample_f = o/2 - 0.25
    int m = o >> 1;
    float kw[4];
    int base;
    if ((o & 1) == 0) {
        base = m - 2;
        kw[0] = -0.0234375f; kw[1] = 0.2265625f; kw[2] = 0.8671875f; kw[3] = -0.0703125f;
    } else {
        base = m - 1;
        kw[0] = -0.0703125f; kw[1] = 0.8671875f; kw[2] = 0.2265625f; kw[3] = -0.0234375f;
    }
    float s = 0.f;
#pragma unroll
    for (int t = 0; t < 4; ++t) {
        int i = base + t;
        bool ok = (i >= 0) && (i < n);
        idx[t] = ok ? i : 0;
        w[t]   = ok ? kw[t] : 0.f;
        s += w[t];
    }
    float inv = 1.f / s;
#pragma unroll
    for (int t = 0; t < 4; ++t) w[t] *= inv;
}

// ---------------- bicubic 2x downsample (separable, fused 16-tap) ----------
__global__ void k_down2(const float* __restrict__ in, float* __restrict__ out1,
                        float* __restrict__ out2, int Cn, int n_in)
{
    int n_out = n_in >> 1;
    long total = (long)Cn * n_out * n_out;
    long t = (long)blockIdx.x * blockDim.x + threadIdx.x;
    if (t >= total) return;
    int ox = (int)(t % n_out);
    int oy = (int)((t / n_out) % n_out);
    long c = t / ((long)n_out * n_out);
    int iy[4], ix[4]; float wy[4], wx[4];
    taps_down2(oy, n_in, iy, wy);
    taps_down2(ox, n_in, ix, wx);
    const float* ip = in + c * n_in * n_in;
    float s = 0.f;
#pragma unroll
    for (int a = 0; a < 4; ++a) {
        float r = 0.f;
#pragma unroll
        for (int b2 = 0; b2 < 4; ++b2) r += wx[b2] * ip[iy[a]*n_in + ix[b2]];
        s += wy[a] * r;
    }
    out1[t] = s;
    if (out2) out2[t] = s;
}

// ---------------- bicubic 2x upsample ---------------------------------------
__global__ void k_up2(const float* __restrict__ in, float* __restrict__ outp,
                      int Cn, int n_in)
{
    int n_out = n_in << 1;
    long total = (long)Cn * n_out * n_out;
    long t = (long)blockIdx.x * blockDim.x + threadIdx.x;
    if (t >= total) return;
    int ox = (int)(t % n_out);
    int oy = (int)((t / n_out) % n_out);
    long c = t / ((long)n_out * n_out);
    int iy[4], ix[4]; float wy[4], wx[4];
    taps_up2(oy, n_in, iy, wy);
    taps_up2(ox, n_in, ix, wx);
    const float* ip = in + c * n_in * n_in;
    float s = 0.f;
#pragma unroll
    for (int a = 0; a < 4; ++a) {
        float r = 0.f;
#pragma unroll
        for (int b2 = 0; b2 < 4; ++b2) r += wx[b2] * ip[iy[a]*n_in + ix[b2]];
        s += wy[a] * r;
    }
    outp[t] = s;
}

// ---------------- layer0: laplacian + rel_coord + W_in matmul --------------
// 64 pixels per block, 256 threads.
__global__ __launch_bounds__(256) void k_layer0(const float* __restrict__ x,
                                                const float* __restrict__ Win)
{
    __shared__ float Ws[896];       // 7 x 128
    __shared__ float inp_s[64][8];
    int tid = threadIdx.x;
    for (int i = tid; i < 896; i += 256) Ws[i] = Win[i];
    long r0 = (long)blockIdx.x * 64;
    if (tid < 64) {
        long r = r0 + tid;
        int b = (int)(r >> 18);
        int n = (int)(r & (HWp - 1));
        int i = n >> 9, j = n & 511;
        int iy[4], ix[4]; float wy[4], wx[4];
        taps_up2(i, DH, iy, wy);
        taps_up2(j, DH, ix, wx);
        float inp[8];
        inp[0] = (i & 1) ? 0.5f : -0.5f;   // rel_coord y
        inp[1] = (j & 1) ? 0.5f : -0.5f;   // rel_coord x
        inp[2] = 1.f; inp[3] = 1.f;        // rel_cell
#pragma unroll
        for (int c = 0; c < 3; ++c) {
            const float* dp = g_down_x + (long)(b*3 + c) * DH * DH;
            float s = 0.f;
#pragma unroll
            for (int a = 0; a < 4; ++a) {
                float rr = 0.f;
#pragma unroll
                for (int b2 = 0; b2 < 4; ++b2) rr += wx[b2] * dp[iy[a]*DH + ix[b2]];
                s += wy[a] * rr;
            }
            inp[4 + c] = x[((long)(b*3 + c) * HH + i) * WW + j] - s;
        }
        inp[7] = 0.f;
#pragma unroll
        for (int q = 0; q < 8; ++q) inp_s[tid][q] = inp[q];
    }
    __syncthreads();
    int o = tid & 127, half = tid >> 7;
#pragma unroll 4
    for (int it = 0; it < 32; ++it) {
        int p = it*2 + half;
        float acc = inp_s[p][0] * Ws[o]
                  + inp_s[p][1] * Ws[128 + o]
                  + inp_s[p][2] * Ws[256 + o]
                  + inp_s[p][3] * Ws[384 + o]
                  + inp_s[p][4] * Ws[512 + o]
                  + inp_s[p][5] * Ws[640 + o]
                  + inp_s[p][6] * Ws[768 + o];
        acc = acc > 0.f ? acc : 0.01f * acc;
        g_actA[(r0 + p) * 128 + o] = acc;
    }
}

// ---------------- 128-wide MLP GEMM: C = [leaky](A @ W) ---------------------
// A: M x 128 (row tile 128 per block), W: 128 x Nw (Nw<=128), C stride Nw.
__global__ __launch_bounds__(256, 2) void mlp_gemm(const float* __restrict__ A,
                                                   const float* __restrict__ Wt,
                                                   float* __restrict__ C,
                                                   int Nw, int doRelu)
{
    __shared__ float As[128][33];
    __shared__ float Bs[32][128];
    const int tid = threadIdx.x;
    const long row0 = (long)blockIdx.x * 128;
    const int ty = tid >> 4;
    const int tx = tid & 15;
    float acc[8][8];
#pragma unroll
    for (int i = 0; i < 8; ++i)
#pragma unroll
        for (int j = 0; j < 8; ++j) acc[i][j] = 0.f;

#pragma unroll 1
    for (int k0 = 0; k0 < 128; k0 += 32) {
        // load A chunk 128x32
#pragma unroll
        for (int it = 0; it < 4; ++it) {
            int idx = it*256 + tid;
            int m = idx >> 3;
            int f4 = idx & 7;
            float4 v = *(const float4*)(A + (row0 + m)*128 + k0 + f4*4);
            As[m][f4*4+0] = v.x; As[m][f4*4+1] = v.y;
            As[m][f4*4+2] = v.z; As[m][f4*4+3] = v.w;
        }
        // load W chunk 32x128 (zero-pad cols beyond Nw)
        if (Nw == 128) {
#pragma unroll
            for (int it = 0; it < 4; ++it) {
                int idx = it*256 + tid;
                int k = idx >> 5;
                int f4 = idx & 31;
                float4 v = *(const float4*)(Wt + (k0 + k)*128 + f4*4);
                *(float4*)&Bs[k][f4*4] = v;
            }
        } else {
#pragma unroll
            for (int it = 0; it < 4; ++it) {
                int idx = it*256 + tid;
                int k = idx >> 5;
                int f4 = idx & 31;
#pragma unroll
                for (int cc = 0; cc < 4; ++cc) {
                    int nn = f4*4 + cc;
                    Bs[k][nn] = (nn < Nw) ? Wt[(k0 + k)*Nw + nn] : 0.f;
                }
            }
        }
        __syncthreads();
#pragma unroll 8
        for (int k = 0; k < 32; ++k) {
            float a[8], b[8];
#pragma unroll
            for (int i = 0; i < 8; ++i) a[i] = As[ty*8 + i][k];
            *(float4*)&b[0] = *(const float4*)&Bs[k][tx*8];
            *(float4*)&b[4] = *(const float4*)&Bs[k][tx*8 + 4];
#pragma unroll
            for (int i = 0; i < 8; ++i)
#pragma unroll
                for (int j = 0; j < 8; ++j)
                    acc[i][j] += a[i] * b[j];
        }
        __syncthreads();
    }
    // epilogue
    if (doRelu) {
#pragma unroll
        for (int i = 0; i < 8; ++i)
#pragma unroll
            for (int j = 0; j < 8; ++j)
                acc[i][j] = acc[i][j] > 0.f ? acc[i][j] : 0.01f * acc[i][j];
    }
    if (Nw == 128) {
#pragma unroll
        for (int i = 0; i < 8; ++i) {
            long r = row0 + ty*8 + i;
            float4 v0 = make_float4(acc[i][0], acc[i][1], acc[i][2], acc[i][3]);
            float4 v1 = make_float4(acc[i][4], acc[i][5], acc[i][6], acc[i][7]);
            *(float4*)(C + r*128 + tx*8)     = v0;
            *(float4*)(C + r*128 + tx*8 + 4) = v1;
        }
    } else {
#pragma unroll
        for (int i = 0; i < 8; ++i) {
            long r = row0 + ty*8 + i;
#pragma unroll
            for (int j = 0; j < 8; ++j) {
                int nn = tx*8 + j;
                if (nn < Nw) C[r*Nw + nn] = acc[i][j];
            }
        }
    }
}

// ---------------- apply local 3x3 dynamic filters ---------------------------
__global__ void k_apply(const float* __restrict__ x, const float* __restrict__ lw,
                        float* __restrict__ outp)
{
    long t = (long)blockIdx.x * 256 + threadIdx.x;
    if (t >= MROWS) return;
    int b = (int)(t >> 18);
    int n = (int)(t & (HWp - 1));
    int i = n >> 9, j = n & 511;
    const float* lwr = lw + t * 81;
    float o0 = 0.f, o1 = 0.f, o2 = 0.f;
#pragma unroll
    for (int c = 0; c < 3; ++c) {
        const float* xp = x + (long)(b*3 + c) * HWp;
#pragma unroll
        for (int ki = 0; ki < 3; ++ki) {
            int yy = i + ki - 1;
#pragma unroll
            for (int kj = 0; kj < 3; ++kj) {
                int xx = j + kj - 1;
                float v = (yy >= 0 && yy < HH && xx >= 0 && xx < WW)
                          ? xp[yy*WW + xx] : 0.f;
                int k = c*9 + ki*3 + kj;
                o0 += v * lwr[k*3 + 0];
                o1 += v * lwr[k*3 + 1];
                o2 += v * lwr[k*3 + 2];
            }
        }
    }
    outp[(long)(b*3 + 0) * HWp + n] = o0;
    outp[(long)(b*3 + 1) * HWp + n] = o1;
    outp[(long)(b*3 + 2) * HWp + n] = o2;
}

// ---------------- 3x3 stride-2 pad-1 conv, 3 -> 64 channels -----------------
__global__ __launch_bounds__(256) void k_conv3x3s2(const float* __restrict__ in,
    const float* __restrict__ wt, const float* __restrict__ bias,
    float* __restrict__ outp, int S)
{
    __shared__ float w_s[1728];
    __shared__ float in_s[3][33][33];
    int tid = threadIdx.x;
    for (int i = tid; i < 1728; i += 256) w_s[i] = wt[i];
    int OS = S >> 1;
    int ox0 = blockIdx.x * 16, oy0 = blockIdx.y * 16, b = blockIdx.z;
    for (int idx = tid; idx < 3*33*33; idx += 256) {
        int c = idx / 1089, rem = idx % 1089, r = rem / 33, col = rem % 33;
        int iy = oy0*2 - 1 + r, ix = ox0*2 - 1 + col;
        float v = 0.f;
        if (iy >= 0 && iy < S && ix >= 0 && ix < S)
            v = in[((long)(b*3 + c) * S + iy) * S + ix];
        in_s[c][r][col] = v;
    }
    __syncthreads();
    int ox = tid & 15, oy = tid >> 4;
    float pix[27];
#pragma unroll
    for (int c = 0; c < 3; ++c)
#pragma unroll
        for (int ki = 0; ki < 3; ++ki)
#pragma unroll
            for (int kj = 0; kj < 3; ++kj)
                pix[c*9 + ki*3 + kj] = in_s[c][2*oy + ki][2*ox + kj];
#pragma unroll 4
    for (int oc = 0; oc < 64; ++oc) {
        float acc = bias[oc];
#pragma unroll
        for (int q = 0; q < 27; ++q) acc += pix[q] * w_s[oc*27 + q];
        outp[(((long)b*64 + oc) * OS + oy0 + oy) * OS + ox0 + ox] = acc;
    }
}

// ---------------- 1x1 mod conv: concat(down_x, out256) 6ch -> 3ch -----------
__global__ void k_mod(const float* __restrict__ dx, const float* __restrict__ o256,
                      const float* __restrict__ mw, const float* __restrict__ mb,
                      float* __restrict__ outp)
{
    int t = blockIdx.x * 256 + threadIdx.x;
    if (t >= BB * DH * DH) return;
    int b = t >> 16, p = t & 65535;
    float in6[6];
#pragma unroll
    for (int c = 0; c < 3; ++c) in6[c]     = dx[(b*3 + c)*65536 + p];
#pragma unroll
    for (int c = 0; c < 3; ++c) in6[3 + c] = o256[(b*3 + c)*65536 + p];
#pragma unroll
    for (int oc = 0; oc < 3; ++oc) {
        float a = mb[oc];
#pragma unroll
        for (int ic = 0; ic < 6; ++ic) a += in6[ic] * mw[oc*6 + ic];
        outp[(b*3 + oc)*65536 + p] = a;
    }
}

// ---------------- launch -----------------------------------------------------
extern "C" void kernel_launch(void* const* d_in, const int* in_sizes, int n_in,
                              void* d_out, int out_size)
{
    const float* x      = (const float*)d_in[0];
    const float* W_in   = (const float*)d_in[1];
    const float* W_h1   = (const float*)d_in[2];
    const float* W_h2   = (const float*)d_in[3];
    const float* W_h3   = (const float*)d_in[4];
    const float* W_h4   = (const float*)d_in[5];
    const float* W_out  = (const float*)d_in[6];
    const float* feat_w = (const float*)d_in[7];
    const float* feat_b = (const float*)d_in[8];
    const float* mod_w  = (const float*)d_in[9];
    const float* mod_b  = (const float*)d_in[10];

    float* outF = (float*)d_out;
    // output tuple layout: down_x_mod, hr_feature, new_lr_feature, ori_lr_feature, out
    float* dout_mod = outF;                       // 2*3*256*256   = 393216
    float* dout_hr  = outF + 393216;              // 2*64*256*256  = 8388608
    float* dout_new = outF + 8781824;             // 8388608
    float* dout_ori = outF + 17170432;            // 8388608
    float* dout_out = outF + 25559040;            // 393216

    float *downx, *actA, *actB, *outfull, *out256, *ftmp;
    cudaGetSymbolAddress((void**)&downx,   g_down_x);
    cudaGetSymbolAddress((void**)&actA,    g_actA);
    cudaGetSymbolAddress((void**)&actB,    g_actB);
    cudaGetSymbolAddress((void**)&outfull, g_out_full);
    cudaGetSymbolAddress((void**)&out256,  g_out256);
    cudaGetSymbolAddress((void**)&ftmp,    g_feat_tmp);

    // 1. down_x = bicubic_down2(x)
    k_down2<<<(BB*3*DH*DH + 255)/256, 256>>>(x, downx, nullptr, BB*3, HH);
    // 2. layer0: inp -> act0
    k_layer0<<<MROWS/64, 256>>>(x, W_in);
    // 3. hidden layers + output layer
    mlp_gemm<<<MROWS/128, 256>>>(actA, W_h1, actB, 128, 1);
    mlp_gemm<<<MROWS/128, 256>>>(actB, W_h2, actA, 128, 1);
    mlp_gemm<<<MROWS/128, 256>>>(actA, W_h3, actB, 128, 1);
    mlp_gemm<<<MROWS/128, 256>>>(actB, W_h4, actA, 128, 1);
    mlp_gemm<<<MROWS/128, 256>>>(actA, W_out, actB, 81, 0);
    // 4. dynamic-filter apply -> out_full (512x512)
    k_apply<<<(MROWS + 255)/256, 256>>>(x, actB, outfull);
    // 5. out = down2(out_full); keep copy for mod conv
    k_down2<<<(BB*3*DH*DH + 255)/256, 256>>>(outfull, out256, dout_out, BB*3, HH);
    // 6. down_x_mod = 1x1 conv(concat(down_x, out))
    k_mod<<<(BB*DH*DH + 255)/256, 256>>>(downx, out256, mod_w, mod_b, dout_mod);
    // 7. hr_feature = conv3x3s2(x)
    {
        dim3 g(16, 16, BB);
        k_conv3x3s2<<<g, 256>>>(x, feat_w, feat_b, dout_hr, 512);
    }
    // 8. ori_lr_feature = up2(conv3x3s2(down_x))
    {
        dim3 g(8, 8, BB);
        k_conv3x3s2<<<g, 256>>>(downx, feat_w, feat_b, ftmp, 256);
    }
    k_up2<<<(BB*64*256*256 + 255)/256, 256>>>(ftmp, dout_ori, BB*64, 128);
    // 9. new_lr_feature = up2(conv3x3s2(down_x_mod))
    {
        dim3 g(8, 8, BB);
        k_conv3x3s2<<<g, 256>>>(dout_mod, feat_w, feat_b, ftmp, 256);
    }
    k_up2<<<(BB*64*256*256 + 255)/256, 256>>>(ftmp, dout_new, BB*64, 128);
}

// round 2
// speedup vs baseline: 1.0267x; 1.0267x over previous
#include <cuda_runtime.h>

#define HH 512
#define WW 512
#define DH 256
#define HWp (HH*WW)          // 262144
#define BB 2
#define MROWS (BB*HWp)       // 524288
#define TPAD 132

// ---------------- scratch (device globals; no allocation allowed) ----------
__device__ float g_down_x[BB*3*DH*DH];                 // 1.5 MB
__device__ float g_lw[(size_t)MROWS*81];               // 162 MB local weights
__device__ float g_out_full[BB*3*HH*WW];               // 6 MB
__device__ float g_out256[BB*3*DH*DH];                 // 1.5 MB
__device__ float g_feat_tmp[BB*64*128*128];            // 8 MB

// ---------------- packed f32x2 helpers --------------------------------------
__device__ __forceinline__ unsigned long long ffma2(unsigned long long a,
                                                    unsigned long long b,
                                                    unsigned long long c) {
    unsigned long long d;
    asm("fma.rn.f32x2 %0, %1, %2, %3;" : "=l"(d) : "l"(a), "l"(b), "l"(c));
    return d;
}
__device__ __forceinline__ unsigned long long dup2(float a) {
    unsigned long long d;
    asm("mov.b64 %0, {%1, %1};" : "=l"(d) : "f"(a));
    return d;
}
__device__ __forceinline__ float2 unpack2(unsigned long long v) {
    float2 r;
    asm("mov.b64 {%0, %1}, %2;" : "=f"(r.x), "=f"(r.y) : "l"(v));
    return r;
}

// ---------------- bicubic tap helpers (match jax.image.resize, a=-0.5) -----
__device__ __forceinline__ void taps_down2(int o, int n, int idx[4], float w[4]) {
    const float kw0 = -0.0625f, kw1 = 0.5625f;
    float kw[4] = {kw0, kw1, kw1, kw0};
    float s = 0.f;
#pragma unroll
    for (int t = 0; t < 4; ++t) {
        int i = 2*o - 1 + t;
        bool ok = (i >= 0) && (i < n);
        idx[t] = ok ? i : 0;
        w[t]   = ok ? kw[t] : 0.f;
        s += w[t];
    }
    float inv = 1.f / s;
#pragma unroll
    for (int t = 0; t < 4; ++t) w[t] *= inv;
}

__device__ __forceinline__ void taps_up2(int o, int n, int idx[4], float w[4]) {
    int m = o >> 1;
    float kw[4];
    int base;
    if ((o & 1) == 0) {
        base = m - 2;
        kw[0] = -0.0234375f; kw[1] = 0.2265625f; kw[2] = 0.8671875f; kw[3] = -0.0703125f;
    } else {
        base = m - 1;
        kw[0] = -0.0703125f; kw[1] = 0.8671875f; kw[2] = 0.2265625f; kw[3] = -0.0234375f;
    }
    float s = 0.f;
#pragma unroll
    for (int t = 0; t < 4; ++t) {
        int i = base + t;
        bool ok = (i >= 0) && (i < n);
        idx[t] = ok ? i : 0;
        w[t]   = ok ? kw[t] : 0.f;
        s += w[t];
    }
    float inv = 1.f / s;
#pragma unroll
    for (int t = 0; t < 4; ++t) w[t] *= inv;
}

// ---------------- bicubic 2x downsample -------------------------------------
__global__ void k_down2(const float* __restrict__ in, float* __restrict__ out1,
                        float* __restrict__ out2, int Cn, int n_in)
{
    int n_out = n_in >> 1;
    long total = (long)Cn * n_out * n_out;
    long t = (long)blockIdx.x * blockDim.x + threadIdx.x;
    if (t >= total) return;
    int ox = (int)(t % n_out);
    int oy = (int)((t / n_out) % n_out);
    long c = t / ((long)n_out * n_out);
    int iy[4], ix[4]; float wy[4], wx[4];
    taps_down2(oy, n_in, iy, wy);
    taps_down2(ox, n_in, ix, wx);
    const float* ip = in + c * n_in * n_in;
    float s = 0.f;
#pragma unroll
    for (int a = 0; a < 4; ++a) {
        float r = 0.f;
#pragma unroll
        for (int b2 = 0; b2 < 4; ++b2) r += wx[b2] * ip[iy[a]*n_in + ix[b2]];
        s += wy[a] * r;
    }
    out1[t] = s;
    if (out2) out2[t] = s;
}

// ---------------- bicubic 2x upsample ---------------------------------------
__global__ void k_up2(const float* __restrict__ in, float* __restrict__ outp,
                      int Cn, int n_in)
{
    int n_out = n_in << 1;
    long total = (long)Cn * n_out * n_out;
    long t = (long)blockIdx.x * blockDim.x + threadIdx.x;
    if (t >= total) return;
    int ox = (int)(t % n_out);
    int oy = (int)((t / n_out) % n_out);
    long c = t / ((long)n_out * n_out);
    int iy[4], ix[4]; float wy[4], wx[4];
    taps_up2(oy, n_in, iy, wy);
    taps_up2(ox, n_in, ix, wx);
    const float* ip = in + c * n_in * n_in;
    float s = 0.f;
#pragma unroll
    for (int a = 0; a < 4; ++a) {
        float r = 0.f;
#pragma unroll
        for (int b2 = 0; b2 < 4; ++b2) r += wx[b2] * ip[iy[a]*n_in + ix[b2]];
        s += wy[a] * r;
    }
    outp[t] = s;
}

// ---------------- fused 6-layer MLP ------------------------------------------
// One CTA = 128 pixels. Activation tile stays in smem across all layers.
// Packed fma.rn.f32x2 doubles fp32 MAC throughput.
struct SmemT {
    float As[128 * TPAD];     // activation tile [m][k]
    float Bs[64 * TPAD];      // weight chunk   [k][n]
    float inp[128 * 8];       // layer-0 inputs
};

__device__ __forceinline__ void layer128(SmemT* sm, const float* __restrict__ W,
                                         int tid, int ty, int tx,
                                         unsigned long long acc[8][4])
{
#pragma unroll
    for (int i = 0; i < 8; ++i)
#pragma unroll
        for (int j = 0; j < 4; ++j) acc[i][j] = 0ULL;

#pragma unroll 1
    for (int kc = 0; kc < 128; kc += 64) {
        // stage 64x128 weight chunk
#pragma unroll
        for (int it = 0; it < 8; ++it) {
            int idx = it * 256 + tid;          // 2048 float4
            int k = idx >> 5, f = idx & 31;
            float4 v = *(const float4*)(W + (long)(kc + k) * 128 + f * 4);
            *(float4*)&sm->Bs[k * TPAD + f * 4] = v;
        }
        __syncthreads();
#pragma unroll 1
        for (int k4 = 0; k4 < 16; ++k4) {
            float4 a4[8];
#pragma unroll
            for (int i = 0; i < 8; ++i)
                a4[i] = *(const float4*)&sm->As[(ty*8 + i) * TPAD + kc + k4*4];
#pragma unroll
            for (int kk = 0; kk < 4; ++kk) {
                const float* bp = &sm->Bs[(k4*4 + kk) * TPAD + tx*8];
                ulonglong2 bb0 = *(const ulonglong2*)bp;
                ulonglong2 bb1 = *(const ulonglong2*)(bp + 4);
#pragma unroll
                for (int i = 0; i < 8; ++i) {
                    float av = ((const float*)&a4[i])[kk];
                    unsigned long long ad = dup2(av);
                    acc[i][0] = ffma2(ad, bb0.x, acc[i][0]);
                    acc[i][1] = ffma2(ad, bb0.y, acc[i][1]);
                    acc[i][2] = ffma2(ad, bb1.x, acc[i][2]);
                    acc[i][3] = ffma2(ad, bb1.y, acc[i][3]);
                }
            }
        }
        __syncthreads();
    }
}

__global__ __launch_bounds__(256, 2) void fused_mlp(
    const float* __restrict__ x,
    const float* __restrict__ Win,
    const float* __restrict__ W1, const float* __restrict__ W2,
    const float* __restrict__ W3, const float* __restrict__ W4,
    const float* __restrict__ Wout,
    float* __restrict__ lw)
{
    extern __shared__ char smem_raw[];
    SmemT* sm = reinterpret_cast<SmemT*>(smem_raw);
    const int tid = threadIdx.x;
    const int ty = tid >> 4, tx = tid & 15;
    const long row0 = (long)blockIdx.x * 128;

    // ---- stage W_in (7x128) into Bs, compute per-pixel inputs ----
    for (int i = tid; i < 896; i += 256) sm->Bs[i] = Win[i];
    if (tid < 128) {
        long r = row0 + tid;
        int b = (int)(r >> 18);
        int n = (int)(r & (HWp - 1));
        int i = n >> 9, j = n & 511;
        int iy[4], ix[4]; float wy[4], wx[4];
        taps_up2(i, DH, iy, wy);
        taps_up2(j, DH, ix, wx);
        float* ip = &sm->inp[tid * 8];
        ip[0] = (i & 1) ? 0.5f : -0.5f;
        ip[1] = (j & 1) ? 0.5f : -0.5f;
        ip[2] = 1.f; ip[3] = 1.f;
#pragma unroll
        for (int c = 0; c < 3; ++c) {
            const float* dp = g_down_x + (long)(b*3 + c) * DH * DH;
            float s = 0.f;
#pragma unroll
            for (int a = 0; a < 4; ++a) {
                float rr = 0.f;
#pragma unroll
                for (int b2 = 0; b2 < 4; ++b2) rr += wx[b2] * dp[iy[a]*DH + ix[b2]];
                s += wy[a] * rr;
            }
            ip[4 + c] = x[((long)(b*3 + c) * HH + i) * WW + j] - s;
        }
        ip[7] = 0.f;
    }
    __syncthreads();

    // ---- layer 0: 7 -> 128 ----
    {
#pragma unroll
        for (int i = 0; i < 8; ++i) {
            int m = ty*8 + i;
            float a0 = sm->inp[m*8+0], a1 = sm->inp[m*8+1], a2 = sm->inp[m*8+2];
            float a3 = sm->inp[m*8+3], a4v = sm->inp[m*8+4], a5 = sm->inp[m*8+5];
            float a6 = sm->inp[m*8+6];
#pragma unroll
            for (int j = 0; j < 8; ++j) {
                int o = tx*8 + j;
                float acc = a0 * sm->Bs[o]
                          + a1 * sm->Bs[128 + o]
                          + a2 * sm->Bs[256 + o]
                          + a3 * sm->Bs[384 + o]
                          + a4v* sm->Bs[512 + o]
                          + a5 * sm->Bs[640 + o]
                          + a6 * sm->Bs[768 + o];
                acc = acc > 0.f ? acc : 0.01f * acc;
                sm->As[m * TPAD + o] = acc;
            }
        }
    }
    __syncthreads();

    unsigned long long acc[8][4];
    const float* Ws[4] = {W1, W2, W3, W4};
#pragma unroll 1
    for (int L = 0; L < 4; ++L) {
        layer128(sm, Ws[L], tid, ty, tx, acc);
        // leaky + write back into As
#pragma unroll
        for (int i = 0; i < 8; ++i) {
            float* row = &sm->As[(ty*8 + i) * TPAD + tx*8];
#pragma unroll
            for (int jj = 0; jj < 4; ++jj) {
                float2 v = unpack2(acc[i][jj]);
                v.x = v.x > 0.f ? v.x : 0.01f * v.x;
                v.y = v.y > 0.f ? v.y : 0.01f * v.y;
                row[jj*2]     = v.x;
                row[jj*2 + 1] = v.y;
            }
        }
        __syncthreads();
    }

    // ---- output layer 128 -> 81 (weights zero-padded to 128 cols) ----
#pragma unroll
    for (int i = 0; i < 8; ++i)
#pragma unroll
        for (int j = 0; j < 4; ++j) acc[i][j] = 0ULL;
#pragma unroll 1
    for (int kc = 0; kc < 128; kc += 64) {
#pragma unroll 1
        for (int it = 0; it < 32; ++it) {
            int idx = it * 256 + tid;          // 8192 scalars
            int k = idx >> 7, n = idx & 127;
            sm->Bs[k * TPAD + n] = (n < 81) ? Wout[(long)(kc + k) * 81 + n] : 0.f;
        }
        __syncthreads();
#pragma unroll 1
        for (int k4 = 0; k4 < 16; ++k4) {
            float4 a4[8];
#pragma unroll
            for (int i = 0; i < 8; ++i)
                a4[i] = *(const float4*)&sm->As[(ty*8 + i) * TPAD + kc + k4*4];
#pragma unroll
            for (int kk = 0; kk < 4; ++kk) {
                const float* bp = &sm->Bs[(k4*4 + kk) * TPAD + tx*8];
                ulonglong2 bb0 = *(const ulonglong2*)bp;
                ulonglong2 bb1 = *(const ulonglong2*)(bp + 4);
#pragma unroll
                for (int i = 0; i < 8; ++i) {
                    float av = ((const float*)&a4[i])[kk];
                    unsigned long long ad = dup2(av);
                    acc[i][0] = ffma2(ad, bb0.x, acc[i][0]);
                    acc[i][1] = ffma2(ad, bb0.y, acc[i][1]);
                    acc[i][2] = ffma2(ad, bb1.x, acc[i][2]);
                    acc[i][3] = ffma2(ad, bb1.y, acc[i][3]);
                }
            }
        }
        __syncthreads();
    }
#pragma unroll
    for (int i = 0; i < 8; ++i) {
        long r = row0 + ty*8 + i;
#pragma unroll
        for (int jj = 0; jj < 4; ++jj) {
            float2 v = unpack2(acc[i][jj]);
            int n = tx*8 + jj*2;
            if (n < 81)     lw[r*81 + n]     = v.x;
            if (n + 1 < 81) lw[r*81 + n + 1] = v.y;
        }
    }
}

// ---------------- apply local 3x3 dynamic filters ---------------------------
__global__ void k_apply(const float* __restrict__ x, const float* __restrict__ lw,
                        float* __restrict__ outp)
{
    long t = (long)blockIdx.x * 256 + threadIdx.x;
    if (t >= MROWS) return;
    int b = (int)(t >> 18);
    int n = (int)(t & (HWp - 1));
    int i = n >> 9, j = n & 511;
    const float* lwr = lw + t * 81;
    float o0 = 0.f, o1 = 0.f, o2 = 0.f;
#pragma unroll
    for (int c = 0; c < 3; ++c) {
        const float* xp = x + (long)(b*3 + c) * HWp;
#pragma unroll
        for (int ki = 0; ki < 3; ++ki) {
            int yy = i + ki - 1;
#pragma unroll
            for (int kj = 0; kj < 3; ++kj) {
                int xx = j + kj - 1;
                float v = (yy >= 0 && yy < HH && xx >= 0 && xx < WW)
                          ? xp[yy*WW + xx] : 0.f;
                int k = c*9 + ki*3 + kj;
                o0 += v * lwr[k*3 + 0];
                o1 += v * lwr[k*3 + 1];
                o2 += v * lwr[k*3 + 2];
            }
        }
    }
    outp[(long)(b*3 + 0) * HWp + n] = o0;
    outp[(long)(b*3 + 1) * HWp + n] = o1;
    outp[(long)(b*3 + 2) * HWp + n] = o2;
}

// ---------------- 3x3 stride-2 pad-1 conv, 3 -> 64 channels -----------------
__global__ __launch_bounds__(256) void k_conv3x3s2(const float* __restrict__ in,
    const float* __restrict__ wt, const float* __restrict__ bias,
    float* __restrict__ outp, int S)
{
    __shared__ float w_s[1728];
    __shared__ float in_s[3][33][33];
    int tid = threadIdx.x;
    for (int i = tid; i < 1728; i += 256) w_s[i] = wt[i];
    int OS = S >> 1;
    int ox0 = blockIdx.x * 16, oy0 = blockIdx.y * 16, b = blockIdx.z;
    for (int idx = tid; idx < 3*33*33; idx += 256) {
        int c = idx / 1089, rem = idx % 1089, r = rem / 33, col = rem % 33;
        int iy = oy0*2 - 1 + r, ix = ox0*2 - 1 + col;
        float v = 0.f;
        if (iy >= 0 && iy < S && ix >= 0 && ix < S)
            v = in[((long)(b*3 + c) * S + iy) * S + ix];
        in_s[c][r][col] = v;
    }
    __syncthreads();
    int ox = tid & 15, oy = tid >> 4;
    float pix[27];
#pragma unroll
    for (int c = 0; c < 3; ++c)
#pragma unroll
        for (int ki = 0; ki < 3; ++ki)
#pragma unroll
            for (int kj = 0; kj < 3; ++kj)
                pix[c*9 + ki*3 + kj] = in_s[c][2*oy + ki][2*ox + kj];
#pragma unroll 4
    for (int oc = 0; oc < 64; ++oc) {
        float acc = bias[oc];
#pragma unroll
        for (int q = 0; q < 27; ++q) acc += pix[q] * w_s[oc*27 + q];
        outp[(((long)b*64 + oc) * OS + oy0 + oy) * OS + ox0 + ox] = acc;
    }
}

// ---------------- 1x1 mod conv ----------------------------------------------
__global__ void k_mod(const float* __restrict__ dx, const float* __restrict__ o256,
                      const float* __restrict__ mw, const float* __restrict__ mb,
                      float* __restrict__ outp)
{
    int t = blockIdx.x * 256 + threadIdx.x;
    if (t >= BB * DH * DH) return;
    int b = t >> 16, p = t & 65535;
    float in6[6];
#pragma unroll
    for (int c = 0; c < 3; ++c) in6[c]     = dx[(b*3 + c)*65536 + p];
#pragma unroll
    for (int c = 0; c < 3; ++c) in6[3 + c] = o256[(b*3 + c)*65536 + p];
#pragma unroll
    for (int oc = 0; oc < 3; ++oc) {
        float a = mb[oc];
#pragma unroll
        for (int ic = 0; ic < 6; ++ic) a += in6[ic] * mw[oc*6 + ic];
        outp[(b*3 + oc)*65536 + p] = a;
    }
}

// ---------------- launch -----------------------------------------------------
extern "C" void kernel_launch(void* const* d_in, const int* in_sizes, int n_in,
                              void* d_out, int out_size)
{
    const float* x      = (const float*)d_in[0];
    const float* W_in   = (const float*)d_in[1];
    const float* W_h1   = (const float*)d_in[2];
    const float* W_h2   = (const float*)d_in[3];
    const float* W_h3   = (const float*)d_in[4];
    const float* W_h4   = (const float*)d_in[5];
    const float* W_out  = (const float*)d_in[6];
    const float* feat_w = (const float*)d_in[7];
    const float* feat_b = (const float*)d_in[8];
    const float* mod_w  = (const float*)d_in[9];
    const float* mod_b  = (const float*)d_in[10];

    float* outF = (float*)d_out;
    float* dout_mod = outF;                       // 2*3*256*256   = 393216
    float* dout_hr  = outF + 393216;              // 2*64*256*256  = 8388608
    float* dout_new = outF + 8781824;             // 8388608
    float* dout_ori = outF + 17170432;            // 8388608
    float* dout_out = outF + 25559040;            // 393216

    float *downx, *lw, *outfull, *out256, *ftmp;
    cudaGetSymbolAddress((void**)&downx,   g_down_x);
    cudaGetSymbolAddress((void**)&lw,      g_lw);
    cudaGetSymbolAddress((void**)&outfull, g_out_full);
    cudaGetSymbolAddress((void**)&out256,  g_out256);
    cudaGetSymbolAddress((void**)&ftmp,    g_feat_tmp);

    static int smem_set = 0;
    const int SMEM_BYTES = (int)sizeof(SmemT);
    if (!smem_set) {
        cudaFuncSetAttribute(fused_mlp, cudaFuncAttributeMaxDynamicSharedMemorySize,
                             SMEM_BYTES);
        smem_set = 1;
    }

    // 1. down_x = bicubic_down2(x)
    k_down2<<<(BB*3*DH*DH + 255)/256, 256>>>(x, downx, nullptr, BB*3, HH);
    // 2. fused MLP: laplacian + 6 layers -> local weights
    fused_mlp<<<MROWS/128, 256, SMEM_BYTES>>>(x, W_in, W_h1, W_h2, W_h3, W_h4,
                                              W_out, lw);
    // 3. dynamic-filter apply -> out_full (512x512)
    k_apply<<<(MROWS + 255)/256, 256>>>(x, lw, outfull);
    // 4. out = down2(out_full); keep copy for mod conv
    k_down2<<<(BB*3*DH*DH + 255)/256, 256>>>(outfull, out256, dout_out, BB*3, HH);
    // 5. down_x_mod = 1x1 conv(concat(down_x, out))
    k_mod<<<(BB*DH*DH + 255)/256, 256>>>(downx, out256, mod_w, mod_b, dout_mod);
    // 6. hr_feature = conv3x3s2(x)
    {
        dim3 g(16, 16, BB);
        k_conv3x3s2<<<g, 256>>>(x, feat_w, feat_b, dout_hr, 512);
    }
    // 7. ori_lr_feature = up2(conv3x3s2(down_x))
    {
        dim3 g(8, 8, BB);
        k_conv3x3s2<<<g, 256>>>(downx, feat_w, feat_b, ftmp, 256);
    }
    k_up2<<<(BB*64*256*256 + 255)/256, 256>>>(ftmp, dout_ori, BB*64, 128);
    // 8. new_lr_feature = up2(conv3x3s2(down_x_mod))
    {
        dim3 g(8, 8, BB);
        k_conv3x3s2<<<g, 256>>>(dout_mod, feat_w, feat_b, ftmp, 256);
    }
    k_up2<<<(BB*64*256*256 + 255)/256, 256>>>(ftmp, dout_new, BB*64, 128);
}

// round 4
// speedup vs baseline: 2.3110x; 2.2510x over previous
#include <cuda_runtime.h>
#include <cuda_bf16.h>
#include <cstdint>

#define HH 512
#define WW 512
#define DH 256
#define HWp (HH*WW)          // 262144
#define BB 2
#define MROWS (BB*HWp)       // 524288

// ---------------- scratch (device globals; no allocation allowed) ----------
__device__ float g_down_x[BB*3*DH*DH];                     // 1.5 MB
__device__ float g_lw[(size_t)81*MROWS];                   // 162 MB, TRANSPOSED [81][M]
__device__ float g_out_full[BB*3*HH*WW];                   // 6 MB
__device__ float g_out256[BB*3*DH*DH];                     // 1.5 MB
__device__ float g_feat_tmp[BB*64*128*128];                // 8 MB
__device__ __align__(16) __nv_bfloat16 g_wHi[5][16384];    // [k][n] row-major, n padded to 128
__device__ __align__(16) __nv_bfloat16 g_wLo[5][16384];

// ---------------- mma/ldmatrix helpers (base ISA, no "a" features) ---------
__device__ __forceinline__ uint32_t smem_u32(const void* p) {
    uint32_t a;
    asm("{ .reg .u64 t; cvta.to.shared.u64 t, %1; cvt.u32.u64 %0, t; }" : "=r"(a) : "l"(p));
    return a;
}
__device__ __forceinline__ void ldsm_x4(uint32_t addr, uint32_t r[4]) {
    asm volatile("ldmatrix.sync.aligned.m8n8.x4.shared.b16 {%0,%1,%2,%3}, [%4];"
        : "=r"(r[0]), "=r"(r[1]), "=r"(r[2]), "=r"(r[3]) : "r"(addr));
}
__device__ __forceinline__ void ldsm_x4t(uint32_t addr, uint32_t r[4]) {
    asm volatile("ldmatrix.sync.aligned.m8n8.x4.trans.shared.b16 {%0,%1,%2,%3}, [%4];"
        : "=r"(r[0]), "=r"(r[1]), "=r"(r[2]), "=r"(r[3]) : "r"(addr));
}
__device__ __forceinline__ void mma_bf16(float d[4], const uint32_t a[4], const uint32_t* b) {
    asm volatile("mma.sync.aligned.m16n8k16.row.col.f32.bf16.bf16.f32 "
        "{%0,%1,%2,%3}, {%4,%5,%6,%7}, {%8,%9}, {%0,%1,%2,%3};"
        : "+f"(d[0]), "+f"(d[1]), "+f"(d[2]), "+f"(d[3])
        : "r"(a[0]), "r"(a[1]), "r"(a[2]), "r"(a[3]), "r"(b[0]), "r"(b[1]));
}

// ---------------- bicubic tap helpers (match jax.image.resize, a=-0.5) -----
__device__ __forceinline__ void taps_down2(int o, int n, int idx[4], float w[4]) {
    const float kw0 = -0.0625f, kw1 = 0.5625f;
    float kw[4] = {kw0, kw1, kw1, kw0};
    float s = 0.f;
#pragma unroll
    for (int t = 0; t < 4; ++t) {
        int i = 2*o - 1 + t;
        bool ok = (i >= 0) && (i < n);
        idx[t] = ok ? i : 0;
        w[t]   = ok ? kw[t] : 0.f;
        s += w[t];
    }
    float inv = 1.f / s;
#pragma unroll
    for (int t = 0; t < 4; ++t) w[t] *= inv;
}
__device__ __forceinline__ void taps_up2(int o, int n, int idx[4], float w[4]) {
    int m = o >> 1;
    float kw[4];
    int base;
    if ((o & 1) == 0) {
        base = m - 2;
        kw[0] = -0.0234375f; kw[1] = 0.2265625f; kw[2] = 0.8671875f; kw[3] = -0.0703125f;
    } else {
        base = m - 1;
        kw[0] = -0.0703125f; kw[1] = 0.8671875f; kw[2] = 0.2265625f; kw[3] = -0.0234375f;
    }
    float s = 0.f;
#pragma unroll
    for (int t = 0; t < 4; ++t) {
        int i = base + t;
        bool ok = (i >= 0) && (i < n);
        idx[t] = ok ? i : 0;
        w[t]   = ok ? kw[t] : 0.f;
        s += w[t];
    }
    float inv = 1.f / s;
#pragma unroll
    for (int t = 0; t < 4; ++t) w[t] *= inv;
}

// ---------------- bicubic 2x down / up --------------------------------------
__global__ void k_down2(const float* __restrict__ in, float* __restrict__ out1,
                        float* __restrict__ out2, int Cn, int n_in)
{
    int n_out = n_in >> 1;
    long total = (long)Cn * n_out * n_out;
    long t = (long)blockIdx.x * blockDim.x + threadIdx.x;
    if (t >= total) return;
    int ox = (int)(t % n_out);
    int oy = (int)((t / n_out) % n_out);
    long c = t / ((long)n_out * n_out);
    int iy[4], ix[4]; float wy[4], wx[4];
    taps_down2(oy, n_in, iy, wy);
    taps_down2(ox, n_in, ix, wx);
    const float* ip = in + c * n_in * n_in;
    float s = 0.f;
#pragma unroll
    for (int a = 0; a < 4; ++a) {
        float r = 0.f;
#pragma unroll
        for (int b2 = 0; b2 < 4; ++b2) r += wx[b2] * ip[iy[a]*n_in + ix[b2]];
        s += wy[a] * r;
    }
    out1[t] = s;
    if (out2) out2[t] = s;
}
__global__ void k_up2(const float* __restrict__ in, float* __restrict__ outp,
                      int Cn, int n_in)
{
    int n_out = n_in << 1;
    long total = (long)Cn * n_out * n_out;
    long t = (long)blockIdx.x * blockDim.x + threadIdx.x;
    if (t >= total) return;
    int ox = (int)(t % n_out);
    int oy = (int)((t / n_out) % n_out);
    long c = t / ((long)n_out * n_out);
    int iy[4], ix[4]; float wy[4], wx[4];
    taps_up2(oy, n_in, iy, wy);
    taps_up2(ox, n_in, ix, wx);
    const float* ip = in + c * n_in * n_in;
    float s = 0.f;
#pragma unroll
    for (int a = 0; a < 4; ++a) {
        float r = 0.f;
#pragma unroll
        for (int b2 = 0; b2 < 4; ++b2) r += wx[b2] * ip[iy[a]*n_in + ix[b2]];
        s += wy[a] * r;
    }
    outp[t] = s;
}

// ---------------- weight prep: f32 -> (hi,lo) bf16, [k][n] n-padded --------
__global__ void k_prep_w(const float* __restrict__ W1, const float* __restrict__ W2,
                         const float* __restrict__ W3, const float* __restrict__ W4,
                         const float* __restrict__ Wout)
{
    int t = blockIdx.x * 256 + threadIdx.x;     // 5*16384 = 81920
    if (t >= 81920) return;
    int L = t >> 14, r = t & 16383;
    int k = r >> 7, n = r & 127;
    const float* W = (L == 0) ? W1 : (L == 1) ? W2 : (L == 2) ? W3 : (L == 3) ? W4 : Wout;
    float v = (L < 4) ? W[k * 128 + n] : ((n < 81) ? W[k * 81 + n] : 0.f);
    __nv_bfloat16 h = __float2bfloat16(v);
    g_wHi[L][r] = h;
    g_wLo[L][r] = __float2bfloat16(v - __bfloat162float(h));
}

// ---------------- fused 6-layer MLP on mma.sync bf16 hi/lo ------------------
// SMEM: padded rows of 272B (136 bf16) for conflict-free ldmatrix.
#define ROWB 272
#define S_AHI 0
#define S_ALO 34816
#define S_BHI 69632
#define S_BLO 104448
#define S_INP 139264          // 128*8 f32
#define S_WIN 143360          // 7*128 f32
#define S_TOT 146944

__device__ __forceinline__ void st_hilo2(char* smem, int row, int col,
                                         float v0, float v1)
{
    __nv_bfloat16 h0 = __float2bfloat16(v0);
    __nv_bfloat16 h1 = __float2bfloat16(v1);
    __nv_bfloat16 l0 = __float2bfloat16(v0 - __bfloat162float(h0));
    __nv_bfloat16 l1 = __float2bfloat16(v1 - __bfloat162float(h1));
    __nv_bfloat162 hp; hp.x = h0; hp.y = h1;
    __nv_bfloat162 lp; lp.x = l0; lp.y = l1;
    int off = row * ROWB + col * 2;
    *(uint32_t*)(smem + S_AHI + off) = *(uint32_t*)&hp;
    *(uint32_t*)(smem + S_ALO + off) = *(uint32_t*)&lp;
}

__global__ __launch_bounds__(256, 1) void fused_mlp_mma(
    const float* __restrict__ x, const float* __restrict__ Win,
    float* __restrict__ lw)
{
    extern __shared__ __align__(16) char smem[];
    const uint32_t sb = smem_u32(smem);
    const int tid = threadIdx.x;
    const int wid = tid >> 5, lane = tid & 31;
    const long row0 = (long)blockIdx.x * 128;

    // ---- stage W_in, per-pixel inputs ----
    for (int i = tid; i < 896; i += 256) *(float*)(smem + S_WIN + i*4) = Win[i];
    if (tid < 128) {
        long r = row0 + tid;
        int b = (int)(r >> 18);
        int n = (int)(r & (HWp - 1));
        int i = n >> 9, j = n & 511;
        int iy[4], ix[4]; float wy[4], wx[4];
        taps_up2(i, DH, iy, wy);
        taps_up2(j, DH, ix, wx);
        float* ip = (float*)(smem + S_INP) + tid * 8;
        ip[0] = (i & 1) ? 0.5f : -0.5f;
        ip[1] = (j & 1) ? 0.5f : -0.5f;
        ip[2] = 1.f; ip[3] = 1.f;
#pragma unroll
        for (int c = 0; c < 3; ++c) {
            const float* dp = g_down_x + (long)(b*3 + c) * DH * DH;
            float s = 0.f;
#pragma unroll
            for (int a = 0; a < 4; ++a) {
                float rr = 0.f;
#pragma unroll
                for (int b2 = 0; b2 < 4; ++b2) rr += wx[b2] * dp[iy[a]*DH + ix[b2]];
                s += wy[a] * rr;
            }
            ip[4 + c] = x[((long)(b*3 + c) * HH + i) * WW + j] - s;
        }
        ip[7] = 0.f;
    }
    __syncthreads();

    // ---- layer 0 (7 -> 128) SIMT, write A hi/lo ----
    {
        int row = tid >> 1;
        int cbase = (tid & 1) * 64;
        const float* ip = (const float*)(smem + S_INP) + row * 8;
        float a0 = ip[0], a1 = ip[1], a2 = ip[2], a3 = ip[3];
        float a4 = ip[4], a5 = ip[5], a6 = ip[6];
        const float* Wn = (const float*)(smem + S_WIN);
#pragma unroll 8
        for (int c = 0; c < 64; c += 2) {
            int o = cbase + c;
            float v0 = a0*Wn[o] + a1*Wn[128+o] + a2*Wn[256+o] + a3*Wn[384+o]
                     + a4*Wn[512+o] + a5*Wn[640+o] + a6*Wn[768+o];
            float v1 = a0*Wn[o+1] + a1*Wn[128+o+1] + a2*Wn[256+o+1] + a3*Wn[384+o+1]
                     + a4*Wn[512+o+1] + a5*Wn[640+o+1] + a6*Wn[768+o+1];
            v0 = v0 > 0.f ? v0 : 0.01f * v0;
            v1 = v1 > 0.f ? v1 : 0.01f * v1;
            st_hilo2(smem, row, o, v0, v1);
        }
    }

    // ---- warp tiling: 4 (m) x 2 (n); warp tile = 32 rows x 64 cols ----
    const int wm = wid & 3, wn = wid >> 2;
    // A ldmatrix address (per mt, per k): rows wm*32+mt*16+(lane&15), 16B half (lane>>4)
    const uint32_t aAddr = sb + S_AHI + (uint32_t)((wm*32 + (lane & 15)) * ROWB + (lane >> 4) * 16);
    // B ldmatrix address (per np, per k): rows k*16+(lane&15), col block wn*64+np*16, half (lane>>4)
    const uint32_t bAddr = sb + S_BHI + (uint32_t)((lane & 15) * ROWB + (wn*64)*2 + (lane >> 4) * 16);

#pragma unroll 1
    for (int L = 0; L < 5; ++L) {
        // stage layer weights hi/lo into smem padded rows
        {
            const uint4* srcH = (const uint4*)g_wHi[L];
            const uint4* srcL = (const uint4*)g_wLo[L];
#pragma unroll
            for (int it = 0; it < 8; ++it) {
                int idx = it * 256 + tid;         // 2048 uint4 = 16384 bf16
                int row = idx >> 4, col = (idx & 15) * 8;
                *(uint4*)(smem + S_BHI + row * ROWB + col * 2) = srcH[idx];
                *(uint4*)(smem + S_BLO + row * ROWB + col * 2) = srcL[idx];
            }
        }
        __syncthreads();

        float acc[2][8][4];
#pragma unroll
        for (int mt = 0; mt < 2; ++mt)
#pragma unroll
            for (int nt = 0; nt < 8; ++nt)
#pragma unroll
                for (int q = 0; q < 4; ++q) acc[mt][nt][q] = 0.f;

#pragma unroll 1
        for (int k = 0; k < 8; ++k) {
            uint32_t ah[2][4], al[2][4];
#pragma unroll
            for (int mt = 0; mt < 2; ++mt) {
                uint32_t a = aAddr + (uint32_t)(mt * 16 * ROWB + k * 32);
                ldsm_x4(a, ah[mt]);
                ldsm_x4(a + (S_ALO - S_AHI), al[mt]);
            }
#pragma unroll
            for (int np = 0; np < 4; ++np) {
                uint32_t bh[4], bl[4];
                uint32_t b = bAddr + (uint32_t)(k * 16 * ROWB + np * 32);
                ldsm_x4t(b, bh);
                ldsm_x4t(b + (S_BLO - S_BHI), bl);
#pragma unroll
                for (int mt = 0; mt < 2; ++mt) {
                    mma_bf16(acc[mt][np*2],   ah[mt], bh);
                    mma_bf16(acc[mt][np*2+1], ah[mt], bh + 2);
                    mma_bf16(acc[mt][np*2],   ah[mt], bl);
                    mma_bf16(acc[mt][np*2+1], ah[mt], bl + 2);
                    mma_bf16(acc[mt][np*2],   al[mt], bh);
                    mma_bf16(acc[mt][np*2+1], al[mt], bh + 2);
                }
            }
        }
        __syncthreads();   // all warps done reading A before overwriting

        if (L < 4) {
#pragma unroll
            for (int mt = 0; mt < 2; ++mt) {
                int r0 = wm*32 + mt*16 + (lane >> 2);
#pragma unroll
                for (int nt = 0; nt < 8; ++nt) {
                    int c = wn*64 + nt*8 + (lane & 3)*2;
                    float v0 = acc[mt][nt][0], v1 = acc[mt][nt][1];
                    float w0 = acc[mt][nt][2], w1 = acc[mt][nt][3];
                    v0 = v0 > 0.f ? v0 : 0.01f * v0;
                    v1 = v1 > 0.f ? v1 : 0.01f * v1;
                    w0 = w0 > 0.f ? w0 : 0.01f * w0;
                    w1 = w1 > 0.f ? w1 : 0.01f * w1;
                    st_hilo2(smem, r0,     c, v0, v1);
                    st_hilo2(smem, r0 + 8, c, w0, w1);
                }
            }
            __syncthreads();
        } else {
            // output layer: cols >= 81 are zero-padded weights; write transposed
#pragma unroll
            for (int mt = 0; mt < 2; ++mt) {
                long r0 = row0 + wm*32 + mt*16 + (lane >> 2);
#pragma unroll
                for (int nt = 0; nt < 8; ++nt) {
                    int c = wn*64 + nt*8 + (lane & 3)*2;
                    if (c < 81) {
                        lw[(long)c * MROWS + r0]     = acc[mt][nt][0];
                        lw[(long)c * MROWS + r0 + 8] = acc[mt][nt][2];
                    }
                    if (c + 1 < 81) {
                        lw[(long)(c+1) * MROWS + r0]     = acc[mt][nt][1];
                        lw[(long)(c+1) * MROWS + r0 + 8] = acc[mt][nt][3];
                    }
                }
            }
        }
    }
}

// ---------------- apply local 3x3 dynamic filters (lw transposed) -----------
__global__ void k_apply(const float* __restrict__ x, const float* __restrict__ lw,
                        float* __restrict__ outp)
{
    long t = (long)blockIdx.x * 256 + threadIdx.x;
    if (t >= MROWS) return;
    int b = (int)(t >> 18);
    int n = (int)(t & (HWp - 1));
    int i = n >> 9, j = n & 511;
    float o0 = 0.f, o1 = 0.f, o2 = 0.f;
#pragma unroll
    for (int c = 0; c < 3; ++c) {
        const float* xp = x + (long)(b*3 + c) * HWp;
#pragma unroll
        for (int ki = 0; ki < 3; ++ki) {
            int yy = i + ki - 1;
#pragma unroll
            for (int kj = 0; kj < 3; ++kj) {
                int xx = j + kj - 1;
                float v = (yy >= 0 && yy < HH && xx >= 0 && xx < WW)
                          ? xp[yy*WW + xx] : 0.f;
                int k = c*9 + ki*3 + kj;
                o0 += v * lw[(long)(k*3 + 0) * MROWS + t];
                o1 += v * lw[(long)(k*3 + 1) * MROWS + t];
                o2 += v * lw[(long)(k*3 + 2) * MROWS + t];
            }
        }
    }
    outp[(long)(b*3 + 0) * HWp + n] = o0;
    outp[(long)(b*3 + 1) * HWp + n] = o1;
    outp[(long)(b*3 + 2) * HWp + n] = o2;
}

// ---------------- 3x3 stride-2 pad-1 conv, 3 -> 64 channels -----------------
__global__ __launch_bounds__(256) void k_conv3x3s2(const float* __restrict__ in,
    const float* __restrict__ wt, const float* __restrict__ bias,
    float* __restrict__ outp, int S)
{
    __shared__ float w_s[1728];
    __shared__ float in_s[3][33][33];
    int tid = threadIdx.x;
    for (int i = tid; i < 1728; i += 256) w_s[i] = wt[i];
    int OS = S >> 1;
    int ox0 = blockIdx.x * 16, oy0 = blockIdx.y * 16, b = blockIdx.z;
    for (int idx = tid; idx < 3*33*33; idx += 256) {
        int c = idx / 1089, rem = idx % 1089, r = rem / 33, col = rem % 33;
        int iy = oy0*2 - 1 + r, ix = ox0*2 - 1 + col;
        float v = 0.f;
        if (iy >= 0 && iy < S && ix >= 0 && ix < S)
            v = in[((long)(b*3 + c) * S + iy) * S + ix];
        in_s[c][r][col] = v;
    }
    __syncthreads();
    int ox = tid & 15, oy = tid >> 4;
    float pix[27];
#pragma unroll
    for (int c = 0; c < 3; ++c)
#pragma unroll
        for (int ki = 0; ki < 3; ++ki)
#pragma unroll
            for (int kj = 0; kj < 3; ++kj)
                pix[c*9 + ki*3 + kj] = in_s[c][2*oy + ki][2*ox + kj];
#pragma unroll 4
    for (int oc = 0; oc < 64; ++oc) {
        float acc = bias[oc];
#pragma unroll
        for (int q = 0; q < 27; ++q) acc += pix[q] * w_s[oc*27 + q];
        outp[(((long)b*64 + oc) * OS + oy0 + oy) * OS + ox0 + ox] = acc;
    }
}

// ---------------- 1x1 mod conv ----------------------------------------------
__global__ void k_mod(const float* __restrict__ dx, const float* __restrict__ o256,
                      const float* __restrict__ mw, const float* __restrict__ mb,
                      float* __restrict__ outp)
{
    int t = blockIdx.x * 256 + threadIdx.x;
    if (t >= BB * DH * DH) return;
    int b = t >> 16, p = t & 65535;
    float in6[6];
#pragma unroll
    for (int c = 0; c < 3; ++c) in6[c]     = dx[(b*3 + c)*65536 + p];
#pragma unroll
    for (int c = 0; c < 3; ++c) in6[3 + c] = o256[(b*3 + c)*65536 + p];
#pragma unroll
    for (int oc = 0; oc < 3; ++oc) {
        float a = mb[oc];
#pragma unroll
        for (int ic = 0; ic < 6; ++ic) a += in6[ic] * mw[oc*6 + ic];
        outp[(b*3 + oc)*65536 + p] = a;
    }
}

// ---------------- launch -----------------------------------------------------
extern "C" void kernel_launch(void* const* d_in, const int* in_sizes, int n_in,
                              void* d_out, int out_size)
{
    const float* x      = (const float*)d_in[0];
    const float* W_in   = (const float*)d_in[1];
    const float* W_h1   = (const float*)d_in[2];
    const float* W_h2   = (const float*)d_in[3];
    const float* W_h3   = (const float*)d_in[4];
    const float* W_h4   = (const float*)d_in[5];
    const float* W_out  = (const float*)d_in[6];
    const float* feat_w = (const float*)d_in[7];
    const float* feat_b = (const float*)d_in[8];
    const float* mod_w  = (const float*)d_in[9];
    const float* mod_b  = (const float*)d_in[10];

    float* outF = (float*)d_out;
    float* dout_mod = outF;                       // 2*3*256*256   = 393216
    float* dout_hr  = outF + 393216;              // 2*64*256*256  = 8388608
    float* dout_new = outF + 8781824;             // 8388608
    float* dout_ori = outF + 17170432;            // 8388608
    float* dout_out = outF + 25559040;            // 393216

    float *downx, *lw, *outfull, *out256, *ftmp;
    cudaGetSymbolAddress((void**)&downx,   g_down_x);
    cudaGetSymbolAddress((void**)&lw,      g_lw);
    cudaGetSymbolAddress((void**)&outfull, g_out_full);
    cudaGetSymbolAddress((void**)&out256,  g_out256);
    cudaGetSymbolAddress((void**)&ftmp,    g_feat_tmp);

    static int smem_set = 0;
    if (!smem_set) {
        cudaFuncSetAttribute(fused_mlp_mma, cudaFuncAttributeMaxDynamicSharedMemorySize,
                             S_TOT);
        smem_set = 1;
    }

    // 1. down_x = bicubic_down2(x)
    k_down2<<<(BB*3*DH*DH + 255)/256, 256>>>(x, downx, nullptr, BB*3, HH);
    // 2. weight split/prep into bf16 hi/lo [k][n]
    k_prep_w<<<320, 256>>>(W_h1, W_h2, W_h3, W_h4, W_out);
    // 3. fused tensor-core MLP -> local weights (transposed [81][M])
    fused_mlp_mma<<<MROWS/128, 256, S_TOT>>>(x, W_in, lw);
    // 4. dynamic-filter apply -> out_full (512x512)
    k_apply<<<(MROWS + 255)/256, 256>>>(x, lw, outfull);
    // 5. out = down2(out_full); keep copy for mod conv
    k_down2<<<(BB*3*DH*DH + 255)/256, 256>>>(outfull, out256, dout_out, BB*3, HH);
    // 6. down_x_mod = 1x1 conv(concat(down_x, out))
    k_mod<<<(BB*DH*DH + 255)/256, 256>>>(downx, out256, mod_w, mod_b, dout_mod);
    // 7. hr_feature = conv3x3s2(x)
    {
        dim3 g(16, 16, BB);
        k_conv3x3s2<<<g, 256>>>(x, feat_w, feat_b, dout_hr, 512);
    }
    // 8. ori_lr_feature = up2(conv3x3s2(down_x))
    {
        dim3 g(8, 8, BB);
        k_conv3x3s2<<<g, 256>>>(downx, feat_w, feat_b, ftmp, 256);
    }
    k_up2<<<(BB*64*256*256 + 255)/256, 256>>>(ftmp, dout_ori, BB*64, 128);
    // 9. new_lr_feature = up2(conv3x3s2(down_x_mod))
    {
        dim3 g(8, 8, BB);
        k_conv3x3s2<<<g, 256>>>(dout_mod, feat_w, feat_b, ftmp, 256);
    }
    k_up2<<<(BB*64*256*256 + 255)/256, 256>>>(ftmp, dout_new, BB*64, 128);
}